// round 2
// baseline (speedup 1.0000x reference)
#include <cuda_runtime.h>

#define NB 2048   // batch
#define PP 196    // patches
#define DD 768    // patch dim
#define OO 512    // output dim
#define KT 16     // top-k
#define BK 32

__device__ int   g_topk[NB * KT];
__device__ float g_local[NB * OO];

// packed dual-fp32 FMA: c = a*b + c (elementwise on 2 packed floats)
#define FFMA2(c, a, b) asm("fma.rn.f32x2 %0, %1, %2, %0;" : "+l"(c) : "l"(a), "l"(b))

// ---------------------------------------------------------------------------
// Kernel 1: per-patch squared L2 norms (8 warps, float4 streaming) +
// single-warp register-resident top-16 selection.
// ---------------------------------------------------------------------------
__global__ void norm_topk_kernel(const float* __restrict__ pt) {
    int n = blockIdx.x;
    __shared__ float norms[PP];

    const float* base = pt + (size_t)n * PP * DD;
    int warp = threadIdx.x >> 5, lane = threadIdx.x & 31;

    for (int p = warp; p < PP; p += 8) {
        const float4* row = (const float4*)(base + p * DD);
        float s = 0.f;
        #pragma unroll
        for (int j = 0; j < (DD / 4) / 32; j++) {   // 6 iters
            float4 q = row[j * 32 + lane];
            s += q.x * q.x + q.y * q.y + q.z * q.z + q.w * q.w;
        }
        #pragma unroll
        for (int o = 16; o; o >>= 1) s += __shfl_xor_sync(0xffffffffu, s, o);
        if (lane == 0) norms[p] = s;
    }
    __syncthreads();

    if (warp == 0) {
        // lane l owns patches l, l+32, ..., in registers
        float v[7];
        #pragma unroll
        for (int j = 0; j < 7; j++) {
            int p = lane + 32 * j;
            v[j] = (p < PP) ? norms[p] : -1e30f;
        }
        #pragma unroll 1
        for (int it = 0; it < KT; it++) {
            float mx = v[0]; int mj = 0;
            #pragma unroll
            for (int j = 1; j < 7; j++) if (v[j] > mx) { mx = v[j]; mj = j; }
            float bmx = mx; int bl = lane;
            #pragma unroll
            for (int o = 16; o; o >>= 1) {
                float om = __shfl_xor_sync(0xffffffffu, bmx, o);
                int   ol = __shfl_xor_sync(0xffffffffu, bl, o);
                if (om > bmx || (om == bmx && ol < bl)) { bmx = om; bl = ol; }
            }
            int wmj = __shfl_sync(0xffffffffu, mj, bl);
            if (lane == bl) v[mj] = -1e30f;
            if (lane == 0) g_topk[n * KT + it] = bl + 32 * wmj;
        }
    }
}

// ---------------------------------------------------------------------------
// Shared GEMM body: BM=64, BN=128, BK=32, 256 threads, 4x8 micro-tile,
// accumulators packed f32x2 (16 FFMA2 per k-step per thread).
// A staged DUPLICATED ({a,a}) so broadcast operand is one LDS.64.
// ---------------------------------------------------------------------------

// ---------------------------------------------------------------------------
// Kernel 2: gathered GEMM + max over the 16 slots per n
// ---------------------------------------------------------------------------
__global__ void __launch_bounds__(256) gemm_local_kernel(const float* __restrict__ pt,
                                                         const float* __restrict__ Wp) {
    __shared__ __align__(16) float As2[64][66];    // duplicated pairs: [m][2k..2k+1]
    __shared__ __align__(16) float Bs[BK][128];    // [k][o]
    __shared__ int   aoff[64];
    __shared__ float red[16][132];

    int tid = threadIdx.x;
    int bm = blockIdx.y, bn = blockIdx.x;

    if (tid < 64) {
        int m = bm * 64 + tid;                 // n = m>>4, slot = m&15 -> g_topk[m]
        int p = g_topk[m];
        aoff[tid] = ((m >> 4) * PP + p) * DD;
    }
    __syncthreads();

    int tx = tid & 15, ty = tid >> 4;
    int lr = tid >> 2, lk = (tid & 3) * 8;     // A loader
    int rb = tid >> 1, kb = (tid & 1) * 16;    // B loader
    const float* wprow = Wp + (size_t)(bn * 128 + rb) * DD + kb;

    unsigned long long acc[4][4] = {};

    for (int kt = 0; kt < DD; kt += BK) {
        const float4* ap = (const float4*)(pt + aoff[lr] + kt + lk);
        float4 a0 = ap[0], a1 = ap[1];
        float av[8] = {a0.x, a0.y, a0.z, a0.w, a1.x, a1.y, a1.z, a1.w};
        #pragma unroll
        for (int j = 0; j < 8; j++)
            *(float2*)&As2[lr][2 * (lk + j)] = make_float2(av[j], av[j]);

        const float4* bp = (const float4*)(wprow + kt);
        #pragma unroll
        for (int q = 0; q < 4; q++) {
            float4 b = bp[q];
            Bs[kb + q * 4 + 0][rb] = b.x;
            Bs[kb + q * 4 + 1][rb] = b.y;
            Bs[kb + q * 4 + 2][rb] = b.z;
            Bs[kb + q * 4 + 3][rb] = b.w;
        }
        __syncthreads();

        #pragma unroll
        for (int kk = 0; kk < BK; kk++) {
            unsigned long long a0u = *(const unsigned long long*)&As2[ty * 4 + 0][2 * kk];
            unsigned long long a1u = *(const unsigned long long*)&As2[ty * 4 + 1][2 * kk];
            unsigned long long a2u = *(const unsigned long long*)&As2[ty * 4 + 2][2 * kk];
            unsigned long long a3u = *(const unsigned long long*)&As2[ty * 4 + 3][2 * kk];
            const unsigned long long* bptr = (const unsigned long long*)&Bs[kk][tx * 8];
            unsigned long long b0 = bptr[0], b1 = bptr[1], b2 = bptr[2], b3 = bptr[3];
            FFMA2(acc[0][0], a0u, b0); FFMA2(acc[0][1], a0u, b1); FFMA2(acc[0][2], a0u, b2); FFMA2(acc[0][3], a0u, b3);
            FFMA2(acc[1][0], a1u, b0); FFMA2(acc[1][1], a1u, b1); FFMA2(acc[1][2], a1u, b2); FFMA2(acc[1][3], a1u, b3);
            FFMA2(acc[2][0], a2u, b0); FFMA2(acc[2][1], a2u, b1); FFMA2(acc[2][2], a2u, b2); FFMA2(acc[2][3], a2u, b3);
            FFMA2(acc[3][0], a3u, b0); FFMA2(acc[3][1], a3u, b1); FFMA2(acc[3][2], a3u, b2); FFMA2(acc[3][3], a3u, b3);
        }
        __syncthreads();
    }

    // per-thread max over its 4 rows (all within one 16-row n-group: g = ty>>2)
    #pragma unroll
    for (int q = 0; q < 4; q++) {
        float2 m = *(float2*)&acc[0][q];
        #pragma unroll
        for (int i = 1; i < 4; i++) {
            float2 t = *(float2*)&acc[i][q];
            m.x = fmaxf(m.x, t.x); m.y = fmaxf(m.y, t.y);
        }
        red[ty][tx * 8 + 2 * q]     = m.x;
        red[ty][tx * 8 + 2 * q + 1] = m.y;
    }
    __syncthreads();

    int col = tid & 127;
    #pragma unroll
    for (int g = tid >> 7; g < 4; g += 2) {
        float m = red[g * 4 + 0][col];
        m = fmaxf(m, red[g * 4 + 1][col]);
        m = fmaxf(m, red[g * 4 + 2][col]);
        m = fmaxf(m, red[g * 4 + 3][col]);
        g_local[(size_t)(bm * 4 + g) * OO + bn * 128 + col] = m;
    }
}

// ---------------------------------------------------------------------------
// Kernel 3: fusion GEMM  out[n,o] = sum_c [cls|local][n,c] * Wf[o,c]
// M=2048, K=1024, N=512
// ---------------------------------------------------------------------------
__global__ void __launch_bounds__(256) gemm_fuse_kernel(const float* __restrict__ cls,
                                                        const float* __restrict__ Wf,
                                                        float* __restrict__ out) {
    __shared__ __align__(16) float As2[64][66];
    __shared__ __align__(16) float Bs[BK][128];

    int tid = threadIdx.x;
    int bm = blockIdx.y, bn = blockIdx.x;
    int tx = tid & 15, ty = tid >> 4;
    int lr = tid >> 2, lk = (tid & 3) * 8;
    int rb = tid >> 1, kb = (tid & 1) * 16;
    const float* wfrow = Wf + (size_t)(bn * 128 + rb) * (2 * OO) + kb;

    unsigned long long acc[4][4] = {};

    for (int kt = 0; kt < 2 * OO; kt += BK) {
        const float* asrc = (kt < OO)
            ? (cls     + (size_t)(bm * 64 + lr) * OO + kt        + lk)
            : (g_local + (size_t)(bm * 64 + lr) * OO + (kt - OO) + lk);
        float4 a0 = ((const float4*)asrc)[0], a1 = ((const float4*)asrc)[1];
        float av[8] = {a0.x, a0.y, a0.z, a0.w, a1.x, a1.y, a1.z, a1.w};
        #pragma unroll
        for (int j = 0; j < 8; j++)
            *(float2*)&As2[lr][2 * (lk + j)] = make_float2(av[j], av[j]);

        const float4* bp = (const float4*)(wfrow + kt);
        #pragma unroll
        for (int q = 0; q < 4; q++) {
            float4 b = bp[q];
            Bs[kb + q * 4 + 0][rb] = b.x;
            Bs[kb + q * 4 + 1][rb] = b.y;
            Bs[kb + q * 4 + 2][rb] = b.z;
            Bs[kb + q * 4 + 3][rb] = b.w;
        }
        __syncthreads();

        #pragma unroll
        for (int kk = 0; kk < BK; kk++) {
            unsigned long long a0u = *(const unsigned long long*)&As2[ty * 4 + 0][2 * kk];
            unsigned long long a1u = *(const unsigned long long*)&As2[ty * 4 + 1][2 * kk];
            unsigned long long a2u = *(const unsigned long long*)&As2[ty * 4 + 2][2 * kk];
            unsigned long long a3u = *(const unsigned long long*)&As2[ty * 4 + 3][2 * kk];
            const unsigned long long* bptr = (const unsigned long long*)&Bs[kk][tx * 8];
            unsigned long long b0 = bptr[0], b1 = bptr[1], b2 = bptr[2], b3 = bptr[3];
            FFMA2(acc[0][0], a0u, b0); FFMA2(acc[0][1], a0u, b1); FFMA2(acc[0][2], a0u, b2); FFMA2(acc[0][3], a0u, b3);
            FFMA2(acc[1][0], a1u, b0); FFMA2(acc[1][1], a1u, b1); FFMA2(acc[1][2], a1u, b2); FFMA2(acc[1][3], a1u, b3);
            FFMA2(acc[2][0], a2u, b0); FFMA2(acc[2][1], a2u, b1); FFMA2(acc[2][2], a2u, b2); FFMA2(acc[2][3], a2u, b3);
            FFMA2(acc[3][0], a3u, b0); FFMA2(acc[3][1], a3u, b1); FFMA2(acc[3][2], a3u, b2); FFMA2(acc[3][3], a3u, b3);
        }
        __syncthreads();
    }

    #pragma unroll
    for (int i = 0; i < 4; i++) {
        int row = bm * 64 + ty * 4 + i;
        float2 f0 = *(float2*)&acc[i][0];
        float2 f1 = *(float2*)&acc[i][1];
        float2 f2 = *(float2*)&acc[i][2];
        float2 f3 = *(float2*)&acc[i][3];
        float* o = out + (size_t)row * OO + bn * 128 + tx * 8;
        *(float4*)o       = make_float4(f0.x, f0.y, f1.x, f1.y);
        *(float4*)(o + 4) = make_float4(f2.x, f2.y, f3.x, f3.y);
    }
}

// ---------------------------------------------------------------------------
// Kernel 4: row L2 normalize in-place
// ---------------------------------------------------------------------------
__global__ void normalize_kernel(float* __restrict__ out) {
    int n = blockIdx.x;
    float* row = out + (size_t)n * OO;
    __shared__ float red[8];

    int t = threadIdx.x;                       // 256 threads, 512 floats
    float2 v = ((float2*)row)[t];
    float s = v.x * v.x + v.y * v.y;
    #pragma unroll
    for (int o = 16; o; o >>= 1) s += __shfl_xor_sync(0xffffffffu, s, o);
    if ((t & 31) == 0) red[t >> 5] = s;
    __syncthreads();
    if (t == 0) {
        float tot = 0.f;
        #pragma unroll
        for (int w = 0; w < 8; w++) tot += red[w];
        red[0] = tot;
    }
    __syncthreads();
    float inv = 1.f / fmaxf(sqrtf(red[0]), 1e-12f);
    v.x *= inv; v.y *= inv;
    ((float2*)row)[t] = v;
}

// ---------------------------------------------------------------------------
extern "C" void kernel_launch(void* const* d_in, const int* in_sizes, int n_in,
                              void* d_out, int out_size) {
    const float* cls = (const float*)d_in[0];   // (2048, 512)
    const float* pt  = (const float*)d_in[1];   // (2048, 196, 768)
    const float* Wp  = (const float*)d_in[2];   // (512, 768)
    const float* Wf  = (const float*)d_in[3];   // (512, 1024)
    float* out = (float*)d_out;                 // (2048, 512)

    norm_topk_kernel<<<NB, 256>>>(pt);
    gemm_local_kernel<<<dim3(OO / 128, NB * KT / 64), 256>>>(pt, Wp);
    gemm_fuse_kernel<<<dim3(OO / 128, NB / 64), 256>>>(cls, Wf, out);
    normalize_kernel<<<NB, 256>>>(out);
}

// round 4
// speedup vs baseline: 2.0358x; 2.0358x over previous
#include <cuda_runtime.h>
#include <cuda_bf16.h>
#include <cstdint>

#define NB 2048   // batch
#define PP 196    // patches
#define DD 768    // patch dim
#define OO 512    // output dim
#define KT 16     // top-k
#define MTOT (NB * KT)   // 32768 gathered rows

// ---------------- device scratch (no allocations allowed) -------------------
__device__ int            g_topk[MTOT];
__device__ float          g_local[NB * OO];
__device__ __nv_bfloat16  g_Ahi[MTOT * DD];        // gathered patches hi
__device__ __nv_bfloat16  g_Alo[MTOT * DD];        // gathered patches lo
__device__ __nv_bfloat16  g_Fhi[NB * 2 * OO];      // fusion input hi
__device__ __nv_bfloat16  g_Flo[NB * 2 * OO];      // fusion input lo
__device__ __nv_bfloat16  g_WpHi[OO * DD];
__device__ __nv_bfloat16  g_WpLo[OO * DD];
__device__ __nv_bfloat16  g_WfHi[OO * 2 * OO];
__device__ __nv_bfloat16  g_WfLo[OO * 2 * OO];

// ---------------- helpers ----------------------------------------------------
__device__ __forceinline__ uint32_t smem_u32(const void* p) {
    uint32_t a;
    asm("{ .reg .u64 t; cvta.to.shared.u64 t, %1; cvt.u32.u64 %0, t; }" : "=r"(a) : "l"(p));
    return a;
}
#define CP_ASYNC16(dst, src) \
    asm volatile("cp.async.cg.shared.global [%0], [%1], 16;" :: "r"(dst), "l"(src) : "memory")
#define CP_COMMIT() asm volatile("cp.async.commit_group;" ::: "memory")
#define CP_WAIT1()  asm volatile("cp.async.wait_group 1;" ::: "memory")
#define LDMATRIX_X4(r, addr) \
    asm volatile("ldmatrix.sync.aligned.m8n8.x4.shared.b16 {%0,%1,%2,%3}, [%4];" \
        : "=r"((r)[0]), "=r"((r)[1]), "=r"((r)[2]), "=r"((r)[3]) : "r"(addr))
#define MMA16816(d, a, b0, b1) \
    asm volatile("mma.sync.aligned.m16n8k16.row.col.f32.bf16.bf16.f32 " \
        "{%0,%1,%2,%3}, {%4,%5,%6,%7}, {%8,%9}, {%0,%1,%2,%3};" \
        : "+f"((d)[0]), "+f"((d)[1]), "+f"((d)[2]), "+f"((d)[3]) \
        : "r"((a)[0]), "r"((a)[1]), "r"((a)[2]), "r"((a)[3]), "r"(b0), "r"(b1))

__device__ __forceinline__ void split_pack(float a, float b, uint32_t& hi, uint32_t& lo) {
    __nv_bfloat16 ha = __float2bfloat16_rn(a), hb = __float2bfloat16_rn(b);
    __nv_bfloat16 la = __float2bfloat16_rn(a - __bfloat162float(ha));
    __nv_bfloat16 lb = __float2bfloat16_rn(b - __bfloat162float(hb));
    __nv_bfloat162 h2 = __nv_bfloat162(ha, hb), l2 = __nv_bfloat162(la, lb);
    hi = *(uint32_t*)&h2; lo = *(uint32_t*)&l2;
}

// ---------------------------------------------------------------------------
// Kernel 0: weight decomposition (hi/lo bf16)
// ---------------------------------------------------------------------------
__global__ void decomp_kernel(const float* __restrict__ Wp, const float* __restrict__ Wf) {
    int i = blockIdx.x * 256 + threadIdx.x;
    const int NWP = OO * DD;
    if (i < NWP) {
        float a = Wp[i];
        __nv_bfloat16 h = __float2bfloat16_rn(a);
        g_WpHi[i] = h;
        g_WpLo[i] = __float2bfloat16_rn(a - __bfloat162float(h));
    } else {
        int j = i - NWP;
        if (j < OO * 2 * OO) {
            float a = Wf[j];
            __nv_bfloat16 h = __float2bfloat16_rn(a);
            g_WfHi[j] = h;
            g_WfLo[j] = __float2bfloat16_rn(a - __bfloat162float(h));
        }
    }
}

// ---------------------------------------------------------------------------
// Kernel 1: per-patch squared L2 norms + single-warp register top-16
// ---------------------------------------------------------------------------
__global__ void norm_topk_kernel(const float* __restrict__ pt) {
    int n = blockIdx.x;
    __shared__ float norms[PP];

    const float* base = pt + (size_t)n * PP * DD;
    int warp = threadIdx.x >> 5, lane = threadIdx.x & 31;

    for (int p = warp; p < PP; p += 8) {
        const float4* row = (const float4*)(base + p * DD);
        float s = 0.f;
        #pragma unroll
        for (int j = 0; j < (DD / 4) / 32; j++) {
            float4 q = row[j * 32 + lane];
            s += q.x * q.x + q.y * q.y + q.z * q.z + q.w * q.w;
        }
        #pragma unroll
        for (int o = 16; o; o >>= 1) s += __shfl_xor_sync(0xffffffffu, s, o);
        if (lane == 0) norms[p] = s;
    }
    __syncthreads();

    if (warp == 0) {
        float v[7];
        #pragma unroll
        for (int j = 0; j < 7; j++) {
            int p = lane + 32 * j;
            v[j] = (p < PP) ? norms[p] : -1e30f;
        }
        #pragma unroll 1
        for (int it = 0; it < KT; it++) {
            float mx = v[0]; int mj = 0;
            #pragma unroll
            for (int j = 1; j < 7; j++) if (v[j] > mx) { mx = v[j]; mj = j; }
            float bmx = mx; int bl = lane;
            #pragma unroll
            for (int o = 16; o; o >>= 1) {
                float om = __shfl_xor_sync(0xffffffffu, bmx, o);
                int   ol = __shfl_xor_sync(0xffffffffu, bl, o);
                if (om > bmx || (om == bmx && ol < bl)) { bmx = om; bl = ol; }
            }
            int wmj = __shfl_sync(0xffffffffu, mj, bl);
            if (lane == bl) v[mj] = -1e30f;
            if (lane == 0) g_topk[n * KT + it] = bl + 32 * wmj;
        }
    }
}

// ---------------------------------------------------------------------------
// Kernel 2: gather selected patches, split fp32 -> bf16 hi/lo, dense layout
// 4 rows per block, 64 threads per row, 3 float4 per thread.
// ---------------------------------------------------------------------------
__global__ void gather_split_kernel(const float* __restrict__ pt) {
    int m = blockIdx.x * 4 + (threadIdx.x >> 6);
    int t = threadIdx.x & 63;
    int p = g_topk[m];
    const float4* src = (const float4*)(pt + ((size_t)(m >> 4) * PP + p) * DD);
    uint2* dhi = (uint2*)(g_Ahi + (size_t)m * DD);
    uint2* dlo = (uint2*)(g_Alo + (size_t)m * DD);
    #pragma unroll
    for (int j = 0; j < 3; j++) {
        int q = t + j * 64;
        float4 v = src[q];
        uint32_t h0, l0, h1, l1;
        split_pack(v.x, v.y, h0, l0);
        split_pack(v.z, v.w, h1, l1);
        dhi[q] = make_uint2(h0, h1);
        dlo[q] = make_uint2(l0, l1);
    }
}

// ---------------------------------------------------------------------------
// Kernel 3/5: bf16 HMMA GEMM, 3-term split. BM=128, BN=256, BK=32, 8 warps,
// warp tile 64x64 (m16n8k16), cp.async double buffer, padded 80B smem rows.
//   C[m, o] = sum_k A[m,k] * B[o,k]   (B row-major [O][K] = col-major KxO)
// MAXEPI: max over 16-row groups -> outp[NB rows]; else plain store.
// Loops 3 terms: (Ahi,Bhi), (Ahi,Blo), (Alo,Bhi).
// ---------------------------------------------------------------------------
#define SM_A_BYTES 10240              // 128 rows * 80B
#define SM_B_BYTES 20480              // 256 rows * 80B
#define SM_BUF     (SM_A_BYTES + SM_B_BYTES)
#define SM_TOTAL   (2 * SM_BUF)

template<int KPT, bool MAXEPI>
__global__ void __launch_bounds__(256, 1) gemm_mma(
    const __nv_bfloat16* __restrict__ Ahi, const __nv_bfloat16* __restrict__ Alo,
    const __nv_bfloat16* __restrict__ Bhi, const __nv_bfloat16* __restrict__ Blo,
    int ldk, float* __restrict__ outp)
{
    extern __shared__ char smem[];
    const int NCH = 3 * KPT;
    uint32_t sb = smem_u32(smem);
    int tid = threadIdx.x, lane = tid & 31, wid = tid >> 5;
    int bn = blockIdx.x, bm = blockIdx.y;
    int warp_m = wid & 1, warp_n = wid >> 1;

    // ---- async tile loader for chunk c into buffer b
    auto issue = [&](int c, int b) {
        int pterm = c / KPT, kt = (c % KPT) * 32;
        const __nv_bfloat16* As = (pterm == 2) ? Alo : Ahi;
        const __nv_bfloat16* Bs = (pterm == 1) ? Blo : Bhi;
        uint32_t abase = sb + b * SM_BUF;
        uint32_t bbase = abase + SM_A_BYTES;
        #pragma unroll
        for (int i = 0; i < 2; i++) {
            int idx = i * 256 + tid, r = idx >> 2, q = idx & 3;
            CP_ASYNC16(abase + r * 80 + q * 16,
                       (const char*)(As + (size_t)(bm * 128 + r) * ldk + kt) + q * 16);
        }
        #pragma unroll
        for (int i = 0; i < 4; i++) {
            int idx = i * 256 + tid, r = idx >> 2, q = idx & 3;
            CP_ASYNC16(bbase + r * 80 + q * 16,
                       (const char*)(Bs + (size_t)(bn * 256 + r) * ldk + kt) + q * 16);
        }
        CP_COMMIT();
    };

    float acc[4][8][4] = {};

    issue(0, 0);
    issue(1, 1);

    for (int c = 0; c < NCH; c++) {
        CP_WAIT1();
        __syncthreads();
        uint32_t abase = sb + (c & 1) * SM_BUF;
        uint32_t bbase = abase + SM_A_BYTES;

        #pragma unroll
        for (int ks = 0; ks < 2; ks++) {
            uint32_t a[4][4], b[4][4];
            #pragma unroll
            for (int mf = 0; mf < 4; mf++) {
                uint32_t addr = abase + (warp_m * 64 + mf * 16 + (lane & 15)) * 80
                              + ((lane >> 4) * 8 + ks * 16) * 2;
                LDMATRIX_X4(a[mf], addr);
            }
            #pragma unroll
            for (int nb = 0; nb < 4; nb++) {
                uint32_t addr = bbase
                    + (warp_n * 64 + nb * 16 + (lane & 7) + ((lane >> 4) & 1) * 8) * 80
                    + (ks * 16 + ((lane >> 3) & 1) * 8) * 2;
                LDMATRIX_X4(b[nb], addr);
            }
            #pragma unroll
            for (int mf = 0; mf < 4; mf++)
                #pragma unroll
                for (int nf = 0; nf < 8; nf++)
                    MMA16816(acc[mf][nf], a[mf], b[nf >> 1][(nf & 1) * 2], b[nf >> 1][(nf & 1) * 2 + 1]);
        }
        __syncthreads();
        if (c + 2 < NCH) issue(c + 2, c & 1); else CP_COMMIT();
    }

    if (MAXEPI) {
        // rows gr and gr+8 of each mf-frag are in the same 16-row group
        #pragma unroll
        for (int mf = 0; mf < 4; mf++) {
            int nrow = bm * 8 + warp_m * 4 + mf;      // batch index
            #pragma unroll
            for (int nf = 0; nf < 8; nf++) {
                float m0 = fmaxf(acc[mf][nf][0], acc[mf][nf][2]);
                float m1 = fmaxf(acc[mf][nf][1], acc[mf][nf][3]);
                #pragma unroll
                for (int o = 4; o < 32; o <<= 1) {
                    m0 = fmaxf(m0, __shfl_xor_sync(0xffffffffu, m0, o));
                    m1 = fmaxf(m1, __shfl_xor_sync(0xffffffffu, m1, o));
                }
                if (lane < 4) {
                    int col = bn * 256 + warp_n * 64 + nf * 8 + lane * 2;
                    *(float2*)&outp[(size_t)nrow * OO + col] = make_float2(m0, m1);
                }
            }
        }
    } else {
        #pragma unroll
        for (int mf = 0; mf < 4; mf++) {
            int r0 = bm * 128 + warp_m * 64 + mf * 16 + (lane >> 2);
            #pragma unroll
            for (int nf = 0; nf < 8; nf++) {
                int col = bn * 256 + warp_n * 64 + nf * 8 + (lane & 3) * 2;
                *(float2*)&outp[(size_t)r0 * OO + col] =
                    make_float2(acc[mf][nf][0], acc[mf][nf][1]);
                *(float2*)&outp[(size_t)(r0 + 8) * OO + col] =
                    make_float2(acc[mf][nf][2], acc[mf][nf][3]);
            }
        }
    }
}

// ---------------------------------------------------------------------------
// Kernel 4: build fusion input [cls | g_local] as bf16 hi/lo
// ---------------------------------------------------------------------------
__global__ void fuse_split_kernel(const float* __restrict__ cls) {
    int n = blockIdx.x, t = threadIdx.x;          // 256 threads, 1024 cols
    int c = t * 4;
    const float4* src = (c < OO)
        ? (const float4*)(cls + (size_t)n * OO + c)
        : (const float4*)(g_local + (size_t)n * OO + (c - OO));
    float4 v = *src;
    uint32_t h0, l0, h1, l1;
    split_pack(v.x, v.y, h0, l0);
    split_pack(v.z, v.w, h1, l1);
    ((uint2*)(g_Fhi + (size_t)n * 2 * OO))[t] = make_uint2(h0, h1);
    ((uint2*)(g_Flo + (size_t)n * 2 * OO))[t] = make_uint2(l0, l1);
}

// ---------------------------------------------------------------------------
// Kernel 6: row L2 normalize in-place
// ---------------------------------------------------------------------------
__global__ void normalize_kernel(float* __restrict__ out) {
    int n = blockIdx.x;
    float* row = out + (size_t)n * OO;
    __shared__ float red[8];

    int t = threadIdx.x;
    float2 v = ((float2*)row)[t];
    float s = v.x * v.x + v.y * v.y;
    #pragma unroll
    for (int o = 16; o; o >>= 1) s += __shfl_xor_sync(0xffffffffu, s, o);
    if ((t & 31) == 0) red[t >> 5] = s;
    __syncthreads();
    if (t == 0) {
        float tot = 0.f;
        #pragma unroll
        for (int w = 0; w < 8; w++) tot += red[w];
        red[0] = tot;
    }
    __syncthreads();
    float inv = 1.f / fmaxf(sqrtf(red[0]), 1e-12f);
    v.x *= inv; v.y *= inv;
    ((float2*)row)[t] = v;
}

// ---------------------------------------------------------------------------
extern "C" void kernel_launch(void* const* d_in, const int* in_sizes, int n_in,
                              void* d_out, int out_size) {
    const float* cls = (const float*)d_in[0];   // (2048, 512)
    const float* pt  = (const float*)d_in[1];   // (2048, 196, 768)
    const float* Wp  = (const float*)d_in[2];   // (512, 768)
    const float* Wf  = (const float*)d_in[3];   // (512, 1024)
    float* out = (float*)d_out;                 // (2048, 512)

    __nv_bfloat16 *ahi, *alo, *fhi, *flo, *wph, *wpl, *wfh, *wfl;
    float* loc;
    cudaGetSymbolAddress((void**)&ahi, g_Ahi);
    cudaGetSymbolAddress((void**)&alo, g_Alo);
    cudaGetSymbolAddress((void**)&fhi, g_Fhi);
    cudaGetSymbolAddress((void**)&flo, g_Flo);
    cudaGetSymbolAddress((void**)&wph, g_WpHi);
    cudaGetSymbolAddress((void**)&wpl, g_WpLo);
    cudaGetSymbolAddress((void**)&wfh, g_WfHi);
    cudaGetSymbolAddress((void**)&wfl, g_WfLo);
    cudaGetSymbolAddress((void**)&loc, g_local);

    cudaFuncSetAttribute(gemm_mma<DD / 32, true>,
                         cudaFuncAttributeMaxDynamicSharedMemorySize, SM_TOTAL);
    cudaFuncSetAttribute(gemm_mma<(2 * OO) / 32, false>,
                         cudaFuncAttributeMaxDynamicSharedMemorySize, SM_TOTAL);

    decomp_kernel<<<(OO * DD + OO * 2 * OO + 255) / 256, 256>>>(Wp, Wf);
    norm_topk_kernel<<<NB, 256>>>(pt);
    gather_split_kernel<<<MTOT / 4, 256>>>(pt);
    gemm_mma<DD / 32, true><<<dim3(OO / 256, MTOT / 128), 256, SM_TOTAL>>>(
        ahi, alo, wph, wpl, DD, loc);
    fuse_split_kernel<<<NB, 256>>>(cls);
    gemm_mma<(2 * OO) / 32, false><<<dim3(OO / 256, NB / 128), 256, SM_TOTAL>>>(
        fhi, flo, wfh, wfl, 2 * OO, out);
    normalize_kernel<<<NB, 256>>>(out);
}

// round 5
// speedup vs baseline: 2.4658x; 1.2112x over previous
#include <cuda_runtime.h>
#include <cuda_bf16.h>
#include <cstdint>

#define NB 2048   // batch
#define PP 196    // patches
#define DD 768    // patch dim
#define OO 512    // output dim
#define KT 16     // top-k
#define MTOT (NB * KT)   // 32768 gathered rows

// ---------------- device scratch (no allocations allowed) -------------------
__device__ int            g_topk[MTOT];
__device__ float          g_local[NB * OO];
__device__ __nv_bfloat16  g_Ahi[MTOT * DD];        // gathered patches hi
__device__ __nv_bfloat16  g_Alo[MTOT * DD];        // gathered patches lo
__device__ __nv_bfloat16  g_Fhi[NB * 2 * OO];      // fusion input hi
__device__ __nv_bfloat16  g_Flo[NB * 2 * OO];      // fusion input lo
__device__ __nv_bfloat16  g_WpHi[OO * DD];
__device__ __nv_bfloat16  g_WpLo[OO * DD];
__device__ __nv_bfloat16  g_WfHi[OO * 2 * OO];
__device__ __nv_bfloat16  g_WfLo[OO * 2 * OO];

// ---------------- helpers ----------------------------------------------------
__device__ __forceinline__ uint32_t smem_u32(const void* p) {
    uint32_t a;
    asm("{ .reg .u64 t; cvta.to.shared.u64 t, %1; cvt.u32.u64 %0, t; }" : "=r"(a) : "l"(p));
    return a;
}
#define CP_ASYNC16(dst, src) \
    asm volatile("cp.async.cg.shared.global [%0], [%1], 16;" :: "r"(dst), "l"(src) : "memory")
#define CP_COMMIT() asm volatile("cp.async.commit_group;" ::: "memory")
#define CP_WAIT2()  asm volatile("cp.async.wait_group 2;" ::: "memory")
#define LDMATRIX_X4(r, addr) \
    asm volatile("ldmatrix.sync.aligned.m8n8.x4.shared.b16 {%0,%1,%2,%3}, [%4];" \
        : "=r"((r)[0]), "=r"((r)[1]), "=r"((r)[2]), "=r"((r)[3]) : "r"(addr))
#define MMA16816(d, a, b0, b1) \
    asm volatile("mma.sync.aligned.m16n8k16.row.col.f32.bf16.bf16.f32 " \
        "{%0,%1,%2,%3}, {%4,%5,%6,%7}, {%8,%9}, {%0,%1,%2,%3};" \
        : "+f"((d)[0]), "+f"((d)[1]), "+f"((d)[2]), "+f"((d)[3]) \
        : "r"((a)[0]), "r"((a)[1]), "r"((a)[2]), "r"((a)[3]), "r"(b0), "r"(b1))

__device__ __forceinline__ void split_pack(float a, float b, uint32_t& hi, uint32_t& lo) {
    __nv_bfloat16 ha = __float2bfloat16_rn(a), hb = __float2bfloat16_rn(b);
    __nv_bfloat16 la = __float2bfloat16_rn(a - __bfloat162float(ha));
    __nv_bfloat16 lb = __float2bfloat16_rn(b - __bfloat162float(hb));
    __nv_bfloat162 h2 = __nv_bfloat162(ha, hb), l2 = __nv_bfloat162(la, lb);
    hi = *(uint32_t*)&h2; lo = *(uint32_t*)&l2;
}

// ---------------------------------------------------------------------------
// Kernel 0: weight decomposition (hi/lo bf16)
// ---------------------------------------------------------------------------
__global__ void decomp_kernel(const float* __restrict__ Wp, const float* __restrict__ Wf) {
    int i = blockIdx.x * 256 + threadIdx.x;
    const int NWP = OO * DD;
    if (i < NWP) {
        float a = Wp[i];
        __nv_bfloat16 h = __float2bfloat16_rn(a);
        g_WpHi[i] = h;
        g_WpLo[i] = __float2bfloat16_rn(a - __bfloat162float(h));
    } else {
        int j = i - NWP;
        if (j < OO * 2 * OO) {
            float a = Wf[j];
            __nv_bfloat16 h = __float2bfloat16_rn(a);
            g_WfHi[j] = h;
            g_WfLo[j] = __float2bfloat16_rn(a - __bfloat162float(h));
        }
    }
}

// ---------------------------------------------------------------------------
// Kernel 1: per-patch squared L2 norms + single-warp register top-16
// ---------------------------------------------------------------------------
__global__ void norm_topk_kernel(const float* __restrict__ pt) {
    int n = blockIdx.x;
    __shared__ float norms[PP];

    const float* base = pt + (size_t)n * PP * DD;
    int warp = threadIdx.x >> 5, lane = threadIdx.x & 31;

    for (int p = warp; p < PP; p += 8) {
        const float4* row = (const float4*)(base + p * DD);
        float s = 0.f;
        #pragma unroll
        for (int j = 0; j < (DD / 4) / 32; j++) {
            float4 q = row[j * 32 + lane];
            s += q.x * q.x + q.y * q.y + q.z * q.z + q.w * q.w;
        }
        #pragma unroll
        for (int o = 16; o; o >>= 1) s += __shfl_xor_sync(0xffffffffu, s, o);
        if (lane == 0) norms[p] = s;
    }
    __syncthreads();

    if (warp == 0) {
        float v[7];
        #pragma unroll
        for (int j = 0; j < 7; j++) {
            int p = lane + 32 * j;
            v[j] = (p < PP) ? norms[p] : -1e30f;
        }
        #pragma unroll 1
        for (int it = 0; it < KT; it++) {
            float mx = v[0]; int mj = 0;
            #pragma unroll
            for (int j = 1; j < 7; j++) if (v[j] > mx) { mx = v[j]; mj = j; }
            float bmx = mx; int bl = lane;
            #pragma unroll
            for (int o = 16; o; o >>= 1) {
                float om = __shfl_xor_sync(0xffffffffu, bmx, o);
                int   ol = __shfl_xor_sync(0xffffffffu, bl, o);
                if (om > bmx || (om == bmx && ol < bl)) { bmx = om; bl = ol; }
            }
            int wmj = __shfl_sync(0xffffffffu, mj, bl);
            if (lane == bl) v[mj] = -1e30f;
            if (lane == 0) g_topk[n * KT + it] = bl + 32 * wmj;
        }
    }
}

// ---------------------------------------------------------------------------
// Kernel 2: gather selected patches, split fp32 -> bf16 hi/lo, dense layout
// ---------------------------------------------------------------------------
__global__ void gather_split_kernel(const float* __restrict__ pt) {
    int m = blockIdx.x * 4 + (threadIdx.x >> 6);
    int t = threadIdx.x & 63;
    int p = g_topk[m];
    const float4* src = (const float4*)(pt + ((size_t)(m >> 4) * PP + p) * DD);
    uint2* dhi = (uint2*)(g_Ahi + (size_t)m * DD);
    uint2* dlo = (uint2*)(g_Alo + (size_t)m * DD);
    #pragma unroll
    for (int j = 0; j < 3; j++) {
        int q = t + j * 64;
        float4 v = src[q];
        uint32_t h0, l0, h1, l1;
        split_pack(v.x, v.y, h0, l0);
        split_pack(v.z, v.w, h1, l1);
        dhi[q] = make_uint2(h0, h1);
        dlo[q] = make_uint2(l0, l1);
    }
}

// ---------------------------------------------------------------------------
// Kernel 3/5: bf16 HMMA GEMM, merged 3-term chunks. BM=128, BN=256, BK=32,
// 8 warps, warp tile 64x64, cp.async 3-stage pipeline, padded 80B smem rows.
// Per chunk: Ahi,Alo,Bhi,Blo staged together; 3 MMA terms accumulate.
// ---------------------------------------------------------------------------
#define SM_A   10240                 // 128 rows * 80B
#define SM_B   20480                 // 256 rows * 80B
#define OFF_AHI 0
#define OFF_ALO SM_A
#define OFF_BHI (2 * SM_A)
#define OFF_BLO (2 * SM_A + SM_B)
#define SM_STAGE (2 * SM_A + 2 * SM_B)   // 61440
#define SM_TOTAL (3 * SM_STAGE)          // 184320

template<int NCH, bool MAXEPI>
__global__ void __launch_bounds__(256, 1) gemm_mma(
    const __nv_bfloat16* __restrict__ Ahi, const __nv_bfloat16* __restrict__ Alo,
    const __nv_bfloat16* __restrict__ Bhi, const __nv_bfloat16* __restrict__ Blo,
    int ldk, float* __restrict__ outp)
{
    extern __shared__ char smem[];
    uint32_t sb = smem_u32(smem);
    int tid = threadIdx.x, lane = tid & 31, wid = tid >> 5;
    int bn = blockIdx.x, bm = blockIdx.y;
    int warp_m = wid & 1, warp_n = wid >> 1;

    // ---- async loader: chunk c into stage buffer b (12 cp.async / thread)
    auto issue = [&](int c, int b) {
        int kt = c * 32;
        uint32_t s0 = sb + b * SM_STAGE;
        #pragma unroll
        for (int i = 0; i < 2; i++) {
            int idx = i * 256 + tid, r = idx >> 2, q = idx & 3;
            const char* sh = (const char*)(Ahi + (size_t)(bm * 128 + r) * ldk + kt) + q * 16;
            const char* sl = (const char*)(Alo + (size_t)(bm * 128 + r) * ldk + kt) + q * 16;
            CP_ASYNC16(s0 + OFF_AHI + r * 80 + q * 16, sh);
            CP_ASYNC16(s0 + OFF_ALO + r * 80 + q * 16, sl);
        }
        #pragma unroll
        for (int i = 0; i < 4; i++) {
            int idx = i * 256 + tid, r = idx >> 2, q = idx & 3;
            const char* sh = (const char*)(Bhi + (size_t)(bn * 256 + r) * ldk + kt) + q * 16;
            const char* sl = (const char*)(Blo + (size_t)(bn * 256 + r) * ldk + kt) + q * 16;
            CP_ASYNC16(s0 + OFF_BHI + r * 80 + q * 16, sh);
            CP_ASYNC16(s0 + OFF_BLO + r * 80 + q * 16, sl);
        }
        CP_COMMIT();
    };

    float acc[4][8][4] = {};

    issue(0, 0);
    issue(1, 1);
    issue(2, 2);

    int buf = 0;
    for (int c = 0; c < NCH; c++) {
        CP_WAIT2();
        __syncthreads();
        uint32_t s0 = sb + buf * SM_STAGE;

        #pragma unroll
        for (int ks = 0; ks < 2; ks++) {
            uint32_t ah[4][4], al[4][4], bb[4][4];
            uint32_t arow = warp_m * 64 + (lane & 15);
            uint32_t acol = ((lane >> 4) * 8 + ks * 16) * 2;
            #pragma unroll
            for (int mf = 0; mf < 4; mf++)
                LDMATRIX_X4(ah[mf], s0 + OFF_AHI + (arow + mf * 16) * 80 + acol);
            #pragma unroll
            for (int mf = 0; mf < 4; mf++)
                LDMATRIX_X4(al[mf], s0 + OFF_ALO + (arow + mf * 16) * 80 + acol);
            uint32_t brow = warp_n * 64 + (lane & 7) + ((lane >> 4) & 1) * 8;
            uint32_t bcol = (ks * 16 + ((lane >> 3) & 1) * 8) * 2;
            #pragma unroll
            for (int nb = 0; nb < 4; nb++)
                LDMATRIX_X4(bb[nb], s0 + OFF_BHI + (brow + nb * 16) * 80 + bcol);
            // term1: Ahi*Bhi, term3: Alo*Bhi
            #pragma unroll
            for (int mf = 0; mf < 4; mf++)
                #pragma unroll
                for (int nf = 0; nf < 8; nf++) {
                    MMA16816(acc[mf][nf], ah[mf], bb[nf >> 1][(nf & 1) * 2], bb[nf >> 1][(nf & 1) * 2 + 1]);
                    MMA16816(acc[mf][nf], al[mf], bb[nf >> 1][(nf & 1) * 2], bb[nf >> 1][(nf & 1) * 2 + 1]);
                }
            // reload b frags with Blo; term2: Ahi*Blo
            #pragma unroll
            for (int nb = 0; nb < 4; nb++)
                LDMATRIX_X4(bb[nb], s0 + OFF_BLO + (brow + nb * 16) * 80 + bcol);
            #pragma unroll
            for (int mf = 0; mf < 4; mf++)
                #pragma unroll
                for (int nf = 0; nf < 8; nf++)
                    MMA16816(acc[mf][nf], ah[mf], bb[nf >> 1][(nf & 1) * 2], bb[nf >> 1][(nf & 1) * 2 + 1]);
        }
        __syncthreads();
        if (c + 3 < NCH) issue(c + 3, buf); else CP_COMMIT();
        buf = (buf == 2) ? 0 : buf + 1;
    }

    if (MAXEPI) {
        #pragma unroll
        for (int mf = 0; mf < 4; mf++) {
            int nrow = bm * 8 + warp_m * 4 + mf;      // batch index
            #pragma unroll
            for (int nf = 0; nf < 8; nf++) {
                float m0 = fmaxf(acc[mf][nf][0], acc[mf][nf][2]);
                float m1 = fmaxf(acc[mf][nf][1], acc[mf][nf][3]);
                #pragma unroll
                for (int o = 4; o < 32; o <<= 1) {
                    m0 = fmaxf(m0, __shfl_xor_sync(0xffffffffu, m0, o));
                    m1 = fmaxf(m1, __shfl_xor_sync(0xffffffffu, m1, o));
                }
                if (lane < 4) {
                    int col = bn * 256 + warp_n * 64 + nf * 8 + lane * 2;
                    *(float2*)&outp[(size_t)nrow * OO + col] = make_float2(m0, m1);
                }
            }
        }
    } else {
        #pragma unroll
        for (int mf = 0; mf < 4; mf++) {
            int r0 = bm * 128 + warp_m * 64 + mf * 16 + (lane >> 2);
            #pragma unroll
            for (int nf = 0; nf < 8; nf++) {
                int col = bn * 256 + warp_n * 64 + nf * 8 + (lane & 3) * 2;
                *(float2*)&outp[(size_t)r0 * OO + col] =
                    make_float2(acc[mf][nf][0], acc[mf][nf][1]);
                *(float2*)&outp[(size_t)(r0 + 8) * OO + col] =
                    make_float2(acc[mf][nf][2], acc[mf][nf][3]);
            }
        }
    }
}

// ---------------------------------------------------------------------------
// Kernel 4: build fusion input [cls | g_local] as bf16 hi/lo
// ---------------------------------------------------------------------------
__global__ void fuse_split_kernel(const float* __restrict__ cls) {
    int n = blockIdx.x, t = threadIdx.x;          // 256 threads, 1024 cols
    int c = t * 4;
    const float4* src = (c < OO)
        ? (const float4*)(cls + (size_t)n * OO + c)
        : (const float4*)(g_local + (size_t)n * OO + (c - OO));
    float4 v = *src;
    uint32_t h0, l0, h1, l1;
    split_pack(v.x, v.y, h0, l0);
    split_pack(v.z, v.w, h1, l1);
    ((uint2*)(g_Fhi + (size_t)n * 2 * OO))[t] = make_uint2(h0, h1);
    ((uint2*)(g_Flo + (size_t)n * 2 * OO))[t] = make_uint2(l0, l1);
}

// ---------------------------------------------------------------------------
// Kernel 6: row L2 normalize in-place
// ---------------------------------------------------------------------------
__global__ void normalize_kernel(float* __restrict__ out) {
    int n = blockIdx.x;
    float* row = out + (size_t)n * OO;
    __shared__ float red[8];

    int t = threadIdx.x;
    float2 v = ((float2*)row)[t];
    float s = v.x * v.x + v.y * v.y;
    #pragma unroll
    for (int o = 16; o; o >>= 1) s += __shfl_xor_sync(0xffffffffu, s, o);
    if ((t & 31) == 0) red[t >> 5] = s;
    __syncthreads();
    if (t == 0) {
        float tot = 0.f;
        #pragma unroll
        for (int w = 0; w < 8; w++) tot += red[w];
        red[0] = tot;
    }
    __syncthreads();
    float inv = 1.f / fmaxf(sqrtf(red[0]), 1e-12f);
    v.x *= inv; v.y *= inv;
    ((float2*)row)[t] = v;
}

// ---------------------------------------------------------------------------
extern "C" void kernel_launch(void* const* d_in, const int* in_sizes, int n_in,
                              void* d_out, int out_size) {
    const float* cls = (const float*)d_in[0];   // (2048, 512)
    const float* pt  = (const float*)d_in[1];   // (2048, 196, 768)
    const float* Wp  = (const float*)d_in[2];   // (512, 768)
    const float* Wf  = (const float*)d_in[3];   // (512, 1024)
    float* out = (float*)d_out;                 // (2048, 512)

    __nv_bfloat16 *ahi, *alo, *fhi, *flo, *wph, *wpl, *wfh, *wfl;
    float* loc;
    cudaGetSymbolAddress((void**)&ahi, g_Ahi);
    cudaGetSymbolAddress((void**)&alo, g_Alo);
    cudaGetSymbolAddress((void**)&fhi, g_Fhi);
    cudaGetSymbolAddress((void**)&flo, g_Flo);
    cudaGetSymbolAddress((void**)&wph, g_WpHi);
    cudaGetSymbolAddress((void**)&wpl, g_WpLo);
    cudaGetSymbolAddress((void**)&wfh, g_WfHi);
    cudaGetSymbolAddress((void**)&wfl, g_WfLo);
    cudaGetSymbolAddress((void**)&loc, g_local);

    cudaFuncSetAttribute(gemm_mma<DD / 32, true>,
                         cudaFuncAttributeMaxDynamicSharedMemorySize, SM_TOTAL);
    cudaFuncSetAttribute(gemm_mma<(2 * OO) / 32, false>,
                         cudaFuncAttributeMaxDynamicSharedMemorySize, SM_TOTAL);

    decomp_kernel<<<(OO * DD + OO * 2 * OO + 255) / 256, 256>>>(Wp, Wf);
    norm_topk_kernel<<<NB, 256>>>(pt);
    gather_split_kernel<<<MTOT / 4, 256>>>(pt);
    gemm_mma<DD / 32, true><<<dim3(OO / 256, MTOT / 128), 256, SM_TOTAL>>>(
        ahi, alo, wph, wpl, DD, loc);
    fuse_split_kernel<<<NB, 256>>>(cls);
    gemm_mma<(2 * OO) / 32, false><<<dim3(OO / 256, NB / 128), 256, SM_TOTAL>>>(
        fhi, flo, wfh, wfl, 2 * OO, out);
    normalize_kernel<<<NB, 256>>>(out);
}